// round 8
// baseline (speedup 1.0000x reference)
#include <cuda_runtime.h>

#define EDGES   65536
#define NODESN  2048
#define DI      64
#define DOUT    64
#define EPSV    1e-6f
#define RCHUNK  32             // rows per scan tile (4096 tiles, R6-proven)
#define CAP     256            // adjacency capacity per node (deg ~ Binom, mean 32)

// scratch (no cudaMalloc allowed)
__device__ int   g_si[EDGES];          // src index per edge
__device__ int   g_ti[EDGES];          // tgt index per edge
__device__ int   g_cnt[NODESN];        // per-target edge count (reset by gather)
__device__ int   g_adj[NODESN * CAP];  // per-target edge lists
__device__ float g_P[NODESN * DOUT];   // x @ Wf_top
__device__ float g_Q[NODESN * DOUT];   // x @ Wf_bot
__device__ float g_u[NODESN];          // x . Ww_top
__device__ float g_v[NODESN];          // x . Ww_bot

// ---------------------------------------------------------------------------
// K0 (k_pre): per-node projections P,Q,u,v. Side stream, fully overlapped
// with the HBM-bound scan (no shared state with it).
// ---------------------------------------------------------------------------
__global__ void __launch_bounds__(256) k_pre(const float* __restrict__ x,
                                             const float* __restrict__ Wf,
                                             const float* __restrict__ Ww) {
    __shared__ float sW[2 * DI * DOUT];   // sW[k*64 + d], 32 KB
    __shared__ float sx[DI * 64];         // sx[k*64 + nl] (transposed), 16 KB

    const int tid = threadIdx.x;
    const int n0 = blockIdx.x * 64;

    {
        const float4* Wf4 = (const float4*)Wf;
        float4* sW4 = (float4*)sW;
#pragma unroll
        for (int i = 0; i < 8; ++i)
            sW4[tid + i * 256] = Wf4[tid + i * 256];
    }
    {
        const float4* x4 = (const float4*)x;
#pragma unroll
        for (int i = 0; i < 4; ++i) {
            int idx = tid + i * 256;          // 0..1023
            int nl = idx >> 4;
            int kq = idx & 15;
            float4 vv = x4[(n0 + nl) * (DI / 4) + kq];
            sx[(kq * 4 + 0) * 64 + nl] = vv.x;
            sx[(kq * 4 + 1) * 64 + nl] = vv.y;
            sx[(kq * 4 + 2) * 64 + nl] = vv.z;
            sx[(kq * 4 + 3) * 64 + nl] = vv.w;
        }
    }
    __syncthreads();

    const int nl = tid >> 2;
    const int dg = (tid & 3) * 16;

    float accP[16] = {}, accQ[16] = {};
    const float4* sW4 = (const float4*)sW;
#pragma unroll 4
    for (int k = 0; k < DI; ++k) {
        float xv = sx[k * 64 + nl];
        int bP = (k * DOUT + dg) >> 2;
        int bQ = ((DI + k) * DOUT + dg) >> 2;
#pragma unroll
        for (int j = 0; j < 4; ++j) {
            float4 w = sW4[bP + j];
            accP[j * 4 + 0] += xv * w.x; accP[j * 4 + 1] += xv * w.y;
            accP[j * 4 + 2] += xv * w.z; accP[j * 4 + 3] += xv * w.w;
            float4 q = sW4[bQ + j];
            accQ[j * 4 + 0] += xv * q.x; accQ[j * 4 + 1] += xv * q.y;
            accQ[j * 4 + 2] += xv * q.z; accQ[j * 4 + 3] += xv * q.w;
        }
    }
    float4* P4 = (float4*)(g_P + (n0 + nl) * DOUT + dg);
    float4* Q4 = (float4*)(g_Q + (n0 + nl) * DOUT + dg);
#pragma unroll
    for (int j = 0; j < 4; ++j) {
        P4[j] = make_float4(accP[j*4+0], accP[j*4+1], accP[j*4+2], accP[j*4+3]);
        Q4[j] = make_float4(accQ[j*4+0], accQ[j*4+1], accQ[j*4+2], accQ[j*4+3]);
    }

    if (tid < 64) {
        float uu = 0.f, vv = 0.f;
#pragma unroll 8
        for (int k = 0; k < DI; ++k) {
            float xv = sx[k * 64 + tid];
            uu += xv * __ldg(&Ww[k]);
            vv += xv * __ldg(&Ww[DI + k]);
        }
        g_u[n0 + tid] = uu;
        g_v[n0 + tid] = vv;
    }
}

// ---------------------------------------------------------------------------
// K1 (k_scan): PURE streaming scan of the 1 GB one-hot pair. No atomics.
// acc = sum (n+1)*v  ->  presence = (acc > 0.5), index = acc - 1 (exact fp32).
// grid (64, 64) = 4096 tiles of 32 rows (R6-measured 88.5% of HBM spec).
// ---------------------------------------------------------------------------
__global__ void __launch_bounds__(256) k_scan(const float4* __restrict__ src4,
                                              const float4* __restrict__ tgt4) {
    const int g4 = blockIdx.x * blockDim.x + threadIdx.x;   // 0..16383
    const int r0 = blockIdx.y * RCHUNK;
    const int stride4 = EDGES / 4;                          // 16384
    size_t base = (size_t)r0 * stride4 + g4;

    float4 ws = {0.f,0.f,0.f,0.f}, wt = {0.f,0.f,0.f,0.f};

#pragma unroll 8
    for (int n = 0; n < RCHUNK; ++n) {
        float fn1 = (float)(r0 + n + 1);
        float4 vs = __ldcs(&src4[base]);
        float4 vt = __ldcs(&tgt4[base]);
        base += stride4;
        ws.x += vs.x * fn1; ws.y += vs.y * fn1; ws.z += vs.z * fn1; ws.w += vs.w * fn1;
        wt.x += vt.x * fn1; wt.y += vt.y * fn1; wt.z += vt.z * fn1; wt.w += vt.w * fn1;
    }
    int e0 = g4 * 4;
    if (ws.x > 0.5f) g_si[e0 + 0] = (int)(ws.x - 0.5f);
    if (ws.y > 0.5f) g_si[e0 + 1] = (int)(ws.y - 0.5f);
    if (ws.z > 0.5f) g_si[e0 + 2] = (int)(ws.z - 0.5f);
    if (ws.w > 0.5f) g_si[e0 + 3] = (int)(ws.w - 0.5f);
    if (wt.x > 0.5f) g_ti[e0 + 0] = (int)(wt.x - 0.5f);
    if (wt.y > 0.5f) g_ti[e0 + 1] = (int)(wt.y - 0.5f);
    if (wt.z > 0.5f) g_ti[e0 + 2] = (int)(wt.z - 0.5f);
    if (wt.w > 0.5f) g_ti[e0 + 3] = (int)(wt.w - 0.5f);
}

// ---------------------------------------------------------------------------
// K2 (k_build): target adjacency lists. One thread per edge; int atomics
// spread over 2048 counters (avg 32 contenders each) — ~2 us.
// ---------------------------------------------------------------------------
__global__ void __launch_bounds__(256) k_build() {
    int e = blockIdx.x * blockDim.x + threadIdx.x;
    int t = g_ti[e];
    int slot = atomicAdd(&g_cnt[t], 1);
    g_adj[t * CAP + slot] = e;
}

// ---------------------------------------------------------------------------
// K3 (k_gather): warp = target node t, lane = 2 output dims.
// acc += ae * relu(P[s]+Q[t]+bf); asum += ae;  out = acc/(asum+eps).
// No float atomics, no div pass. Resets g_cnt for the next graph replay.
// No mean subtraction (softmax shift-invariant; EPS perturbation ~2e-8 rel).
// ---------------------------------------------------------------------------
__global__ void __launch_bounds__(256) k_gather(const float* __restrict__ bf,
                                                const float* __restrict__ bw,
                                                float* __restrict__ out) {
    const int t    = (blockIdx.x * blockDim.x + threadIdx.x) >> 5;  // node
    const int lane = threadIdx.x & 31;
    const int deg  = g_cnt[t];

    float2 q = ((const float2*)g_Q)[t * 32 + lane];
    float2 b = __ldg(&((const float2*)bf)[lane]);
    float  c = q.x + b.x;    // fold per-warp constants
    float  d = q.y + b.y;
    float  vt = g_v[t] + __ldg(bw);

    float2 acc = make_float2(0.f, 0.f);
    float  asum = 0.f;
    const int* adj = g_adj + t * CAP;

    for (int i = 0; i < deg; ++i) {
        int e = adj[i];                       // broadcast load
        int s = g_si[e];
        float ae = expf(g_u[s] + vt);
        float2 p = ((const float2*)g_P)[s * 32 + lane];
        acc.x += ae * fmaxf(p.x + c, 0.f);
        acc.y += ae * fmaxf(p.y + d, 0.f);
        asum  += ae;
    }
    float inv = 1.0f / (asum + EPSV);
    ((float2*)out)[t * 32 + lane] = make_float2(acc.x * inv, acc.y * inv);
    if (lane == 0) g_cnt[t] = 0;              // self-clean for next replay
}

// ---------------------------------------------------------------------------
extern "C" void kernel_launch(void* const* d_in, const int* in_sizes, int n_in,
                              void* d_out, int out_size) {
    const float* x   = (const float*)d_in[0];
    const float* src = (const float*)d_in[1];
    const float* tgt = (const float*)d_in[2];
    const float* Wf  = (const float*)d_in[3];
    const float* bf  = (const float*)d_in[4];
    const float* Ww  = (const float*)d_in[5];
    const float* bw  = (const float*)d_in[6];
    float* out = (float*)d_out;

    // side stream + events, created once on the (uncaptured) first call
    static cudaStream_t s2 = nullptr;
    static cudaEvent_t ev_fork = nullptr, ev_join = nullptr;
    if (s2 == nullptr) {
        cudaStreamCreateWithFlags(&s2, cudaStreamNonBlocking);
        cudaEventCreateWithFlags(&ev_fork, cudaEventDisableTiming);
        cudaEventCreateWithFlags(&ev_join, cudaEventDisableTiming);
    }

    // fork: k_pre (projections) overlaps the HBM-bound scan
    cudaEventRecord(ev_fork, 0);
    cudaStreamWaitEvent(s2, ev_fork, 0);
    k_pre<<<NODESN / 64, 256, 0, s2>>>(x, Wf, Ww);
    cudaEventRecord(ev_join, s2);

    k_scan<<<dim3(EDGES / 4 / 256, NODESN / RCHUNK), 256>>>(
        (const float4*)src, (const float4*)tgt);
    k_build<<<EDGES / 256, 256>>>();

    // join: gather needs scan+build (adjacency, g_si) and pre (P,Q,u,v)
    cudaStreamWaitEvent(0, ev_join, 0);
    k_gather<<<NODESN * 32 / 256, 256>>>(bf, bw, out);
}

// round 9
// speedup vs baseline: 1.0960x; 1.0960x over previous
#include <cuda_runtime.h>

#define EDGES   65536
#define NODESN  2048
#define DI      64
#define DOUT    64
#define EPSV    1e-6f
#define RCHUNK  32             // rows per scan tile (4096 tiles, R6-proven)
#define CAP     256            // adjacency capacity per node (deg ~ Binom, mean 32)

// scratch (no cudaMalloc allowed)
__device__ int   g_si[EDGES];          // src index per edge
__device__ int   g_ti[EDGES];          // tgt index per edge
__device__ int   g_cnt[NODESN];        // per-target edge count (reset by gather)
__device__ int   g_adj[NODESN * CAP];  // per-target SOURCE-NODE lists
__device__ float g_P[NODESN * DOUT];   // x @ Wf_top
__device__ float g_Q[NODESN * DOUT];   // x @ Wf_bot
__device__ float g_eu[NODESN];         // exp(x . Ww_top)
__device__ float g_v[NODESN];          // x . Ww_bot

// ---------------------------------------------------------------------------
// K0 (k_pre): per-node projections P,Q,exp(u),v. Side stream, fully
// overlapped with the HBM-bound scan (no shared state with it).
// ---------------------------------------------------------------------------
__global__ void __launch_bounds__(256) k_pre(const float* __restrict__ x,
                                             const float* __restrict__ Wf,
                                             const float* __restrict__ Ww) {
    __shared__ float sW[2 * DI * DOUT];   // sW[k*64 + d], 32 KB
    __shared__ float sx[DI * 64];         // sx[k*64 + nl] (transposed), 16 KB

    const int tid = threadIdx.x;
    const int n0 = blockIdx.x * 64;

    {
        const float4* Wf4 = (const float4*)Wf;
        float4* sW4 = (float4*)sW;
#pragma unroll
        for (int i = 0; i < 8; ++i)
            sW4[tid + i * 256] = Wf4[tid + i * 256];
    }
    {
        const float4* x4 = (const float4*)x;
#pragma unroll
        for (int i = 0; i < 4; ++i) {
            int idx = tid + i * 256;          // 0..1023
            int nl = idx >> 4;
            int kq = idx & 15;
            float4 vv = x4[(n0 + nl) * (DI / 4) + kq];
            sx[(kq * 4 + 0) * 64 + nl] = vv.x;
            sx[(kq * 4 + 1) * 64 + nl] = vv.y;
            sx[(kq * 4 + 2) * 64 + nl] = vv.z;
            sx[(kq * 4 + 3) * 64 + nl] = vv.w;
        }
    }
    __syncthreads();

    const int nl = tid >> 2;
    const int dg = (tid & 3) * 16;

    float accP[16] = {}, accQ[16] = {};
    const float4* sW4 = (const float4*)sW;
#pragma unroll 4
    for (int k = 0; k < DI; ++k) {
        float xv = sx[k * 64 + nl];
        int bP = (k * DOUT + dg) >> 2;
        int bQ = ((DI + k) * DOUT + dg) >> 2;
#pragma unroll
        for (int j = 0; j < 4; ++j) {
            float4 w = sW4[bP + j];
            accP[j * 4 + 0] += xv * w.x; accP[j * 4 + 1] += xv * w.y;
            accP[j * 4 + 2] += xv * w.z; accP[j * 4 + 3] += xv * w.w;
            float4 q = sW4[bQ + j];
            accQ[j * 4 + 0] += xv * q.x; accQ[j * 4 + 1] += xv * q.y;
            accQ[j * 4 + 2] += xv * q.z; accQ[j * 4 + 3] += xv * q.w;
        }
    }
    float4* P4 = (float4*)(g_P + (n0 + nl) * DOUT + dg);
    float4* Q4 = (float4*)(g_Q + (n0 + nl) * DOUT + dg);
#pragma unroll
    for (int j = 0; j < 4; ++j) {
        P4[j] = make_float4(accP[j*4+0], accP[j*4+1], accP[j*4+2], accP[j*4+3]);
        Q4[j] = make_float4(accQ[j*4+0], accQ[j*4+1], accQ[j*4+2], accQ[j*4+3]);
    }

    if (tid < 64) {
        float uu = 0.f, vv = 0.f;
#pragma unroll 8
        for (int k = 0; k < DI; ++k) {
            float xv = sx[k * 64 + tid];
            uu += xv * __ldg(&Ww[k]);
            vv += xv * __ldg(&Ww[DI + k]);
        }
        g_eu[n0 + tid] = expf(uu);
        g_v[n0 + tid]  = vv;
    }
}

// ---------------------------------------------------------------------------
// K1 (k_scan): PURE streaming scan of the 1 GB one-hot pair. No atomics.
// acc = sum (n+1)*v  ->  presence = (acc > 0.5), index = acc - 1 (exact fp32).
// grid (64, 64) = 4096 tiles of 32 rows.
// ---------------------------------------------------------------------------
__global__ void __launch_bounds__(256) k_scan(const float4* __restrict__ src4,
                                              const float4* __restrict__ tgt4) {
    const int g4 = blockIdx.x * blockDim.x + threadIdx.x;   // 0..16383
    const int r0 = blockIdx.y * RCHUNK;
    const int stride4 = EDGES / 4;                          // 16384
    size_t base = (size_t)r0 * stride4 + g4;

    float4 ws = {0.f,0.f,0.f,0.f}, wt = {0.f,0.f,0.f,0.f};

#pragma unroll 8
    for (int n = 0; n < RCHUNK; ++n) {
        float fn1 = (float)(r0 + n + 1);
        float4 vs = __ldcs(&src4[base]);
        float4 vt = __ldcs(&tgt4[base]);
        base += stride4;
        ws.x += vs.x * fn1; ws.y += vs.y * fn1; ws.z += vs.z * fn1; ws.w += vs.w * fn1;
        wt.x += vt.x * fn1; wt.y += vt.y * fn1; wt.z += vt.z * fn1; wt.w += vt.w * fn1;
    }
    int e0 = g4 * 4;
    if (ws.x > 0.5f) g_si[e0 + 0] = (int)(ws.x - 0.5f);
    if (ws.y > 0.5f) g_si[e0 + 1] = (int)(ws.y - 0.5f);
    if (ws.z > 0.5f) g_si[e0 + 2] = (int)(ws.z - 0.5f);
    if (ws.w > 0.5f) g_si[e0 + 3] = (int)(ws.w - 0.5f);
    if (wt.x > 0.5f) g_ti[e0 + 0] = (int)(wt.x - 0.5f);
    if (wt.y > 0.5f) g_ti[e0 + 1] = (int)(wt.y - 0.5f);
    if (wt.z > 0.5f) g_ti[e0 + 2] = (int)(wt.z - 0.5f);
    if (wt.w > 0.5f) g_ti[e0 + 3] = (int)(wt.w - 0.5f);
}

// ---------------------------------------------------------------------------
// K2 (k_build): target adjacency lists storing the SOURCE node id directly
// (kills one indirection level in the gather chain).
// ---------------------------------------------------------------------------
__global__ void __launch_bounds__(256) k_build() {
    int e = blockIdx.x * blockDim.x + threadIdx.x;
    int t = g_ti[e];
    int s = g_si[e];
    int slot = atomicAdd(&g_cnt[t], 1);
    g_adj[t * CAP + slot] = s;
}

// ---------------------------------------------------------------------------
// K3 (k_gather): warp = target node t, lane = 2 output dims.
// ae = eu[s] * exp(v[t]+bw)  (per-warp constant factor, no MUFU in loop).
// acc += ae * relu(P[s]+Q[t]+bf); asum += ae;  out = acc/(asum+eps).
// 4-way unrolled -> 4 independent 2-level load chains in flight.
// Resets g_cnt for the next graph replay.
// ---------------------------------------------------------------------------
__global__ void __launch_bounds__(256) k_gather(const float* __restrict__ bf,
                                                const float* __restrict__ bw,
                                                float* __restrict__ out) {
    const int t    = (blockIdx.x * blockDim.x + threadIdx.x) >> 5;  // node
    const int lane = threadIdx.x & 31;
    const int deg  = g_cnt[t];

    float2 q = ((const float2*)g_Q)[t * 32 + lane];
    float2 b = __ldg(&((const float2*)bf)[lane]);
    const float c = q.x + b.x;          // fold per-warp constants
    const float d = q.y + b.y;
    const float evt = expf(g_v[t] + __ldg(bw));

    float2 acc = make_float2(0.f, 0.f);
    float  asum = 0.f;
    const int* adj = g_adj + t * CAP;
    const float2* P2 = (const float2*)g_P;

    int i = 0;
    for (; i + 4 <= deg; i += 4) {
        int s0 = adj[i + 0], s1 = adj[i + 1], s2 = adj[i + 2], s3 = adj[i + 3];
        float a0 = g_eu[s0], a1 = g_eu[s1], a2 = g_eu[s2], a3 = g_eu[s3];
        float2 p0 = P2[s0 * 32 + lane];
        float2 p1 = P2[s1 * 32 + lane];
        float2 p2 = P2[s2 * 32 + lane];
        float2 p3 = P2[s3 * 32 + lane];
        acc.x += a0 * fmaxf(p0.x + c, 0.f) + a1 * fmaxf(p1.x + c, 0.f)
               + a2 * fmaxf(p2.x + c, 0.f) + a3 * fmaxf(p3.x + c, 0.f);
        acc.y += a0 * fmaxf(p0.y + d, 0.f) + a1 * fmaxf(p1.y + d, 0.f)
               + a2 * fmaxf(p2.y + d, 0.f) + a3 * fmaxf(p3.y + d, 0.f);
        asum  += (a0 + a1) + (a2 + a3);
    }
    for (; i < deg; ++i) {
        int s = adj[i];
        float a = g_eu[s];
        float2 p = P2[s * 32 + lane];
        acc.x += a * fmaxf(p.x + c, 0.f);
        acc.y += a * fmaxf(p.y + d, 0.f);
        asum  += a;
    }

    // ae = eu*evt for every edge: factor evt out of both sums (cancels except eps)
    float inv = evt / (evt * asum + EPSV);
    ((float2*)out)[t * 32 + lane] = make_float2(acc.x * inv, acc.y * inv);
    if (lane == 0) g_cnt[t] = 0;              // self-clean for next replay
}

// ---------------------------------------------------------------------------
extern "C" void kernel_launch(void* const* d_in, const int* in_sizes, int n_in,
                              void* d_out, int out_size) {
    const float* x   = (const float*)d_in[0];
    const float* src = (const float*)d_in[1];
    const float* tgt = (const float*)d_in[2];
    const float* Wf  = (const float*)d_in[3];
    const float* bf  = (const float*)d_in[4];
    const float* Ww  = (const float*)d_in[5];
    const float* bw  = (const float*)d_in[6];
    float* out = (float*)d_out;

    // side stream + events, created once on the (uncaptured) first call
    static cudaStream_t s2 = nullptr;
    static cudaEvent_t ev_fork = nullptr, ev_join = nullptr;
    if (s2 == nullptr) {
        cudaStreamCreateWithFlags(&s2, cudaStreamNonBlocking);
        cudaEventCreateWithFlags(&ev_fork, cudaEventDisableTiming);
        cudaEventCreateWithFlags(&ev_join, cudaEventDisableTiming);
    }

    // fork: k_pre (projections) overlaps the HBM-bound scan
    cudaEventRecord(ev_fork, 0);
    cudaStreamWaitEvent(s2, ev_fork, 0);
    k_pre<<<NODESN / 64, 256, 0, s2>>>(x, Wf, Ww);
    cudaEventRecord(ev_join, s2);

    k_scan<<<dim3(EDGES / 4 / 256, NODESN / RCHUNK), 256>>>(
        (const float4*)src, (const float4*)tgt);
    k_build<<<EDGES / 256, 256>>>();

    // join: gather needs scan+build (adjacency) and pre (P,Q,eu,v)
    cudaStreamWaitEvent(0, ev_join, 0);
    k_gather<<<NODESN * 32 / 256, 256>>>(bf, bw, out);
}

// round 10
// speedup vs baseline: 1.1214x; 1.0232x over previous
#include <cuda_runtime.h>

#define EDGES   65536
#define NODESN  2048
#define DI      64
#define DOUT    64
#define EPSV    1e-6f
#define RCHUNK  32             // rows per scan tile (4096 tiles, R6-proven)
#define CAP     256            // adjacency capacity per node (deg ~ Binom, mean 32)

// scratch (no cudaMalloc allowed)
__device__ int   g_si[EDGES];          // src index per edge
__device__ int   g_ti[EDGES];          // tgt index per edge
__device__ int   g_cnt[NODESN];        // per-target edge count (reset by gather)
__device__ int   g_adj[NODESN * CAP];  // per-target SOURCE-NODE lists
__device__ float g_P[NODESN * DOUT];   // x @ Wf_top
__device__ float g_Q[NODESN * DOUT];   // x @ Wf_bot
__device__ float g_eu[NODESN];         // exp(x . Ww_top)
__device__ float g_v[NODESN];          // x . Ww_bot

// ---------------------------------------------------------------------------
// K0 (k_pre): per-node projections P,Q,exp(u),v. Side stream, fully
// overlapped with the HBM-bound scan (no shared state with it).
// ---------------------------------------------------------------------------
__global__ void __launch_bounds__(256) k_pre(const float* __restrict__ x,
                                             const float* __restrict__ Wf,
                                             const float* __restrict__ Ww) {
    __shared__ float sW[2 * DI * DOUT];   // sW[k*64 + d], 32 KB
    __shared__ float sx[DI * 64];         // sx[k*64 + nl] (transposed), 16 KB

    const int tid = threadIdx.x;
    const int n0 = blockIdx.x * 64;

    {
        const float4* Wf4 = (const float4*)Wf;
        float4* sW4 = (float4*)sW;
#pragma unroll
        for (int i = 0; i < 8; ++i)
            sW4[tid + i * 256] = Wf4[tid + i * 256];
    }
    {
        const float4* x4 = (const float4*)x;
#pragma unroll
        for (int i = 0; i < 4; ++i) {
            int idx = tid + i * 256;          // 0..1023
            int nl = idx >> 4;
            int kq = idx & 15;
            float4 vv = x4[(n0 + nl) * (DI / 4) + kq];
            sx[(kq * 4 + 0) * 64 + nl] = vv.x;
            sx[(kq * 4 + 1) * 64 + nl] = vv.y;
            sx[(kq * 4 + 2) * 64 + nl] = vv.z;
            sx[(kq * 4 + 3) * 64 + nl] = vv.w;
        }
    }
    __syncthreads();

    const int nl = tid >> 2;
    const int dg = (tid & 3) * 16;

    float accP[16] = {}, accQ[16] = {};
    const float4* sW4 = (const float4*)sW;
#pragma unroll 4
    for (int k = 0; k < DI; ++k) {
        float xv = sx[k * 64 + nl];
        int bP = (k * DOUT + dg) >> 2;
        int bQ = ((DI + k) * DOUT + dg) >> 2;
#pragma unroll
        for (int j = 0; j < 4; ++j) {
            float4 w = sW4[bP + j];
            accP[j * 4 + 0] += xv * w.x; accP[j * 4 + 1] += xv * w.y;
            accP[j * 4 + 2] += xv * w.z; accP[j * 4 + 3] += xv * w.w;
            float4 q = sW4[bQ + j];
            accQ[j * 4 + 0] += xv * q.x; accQ[j * 4 + 1] += xv * q.y;
            accQ[j * 4 + 2] += xv * q.z; accQ[j * 4 + 3] += xv * q.w;
        }
    }
    float4* P4 = (float4*)(g_P + (n0 + nl) * DOUT + dg);
    float4* Q4 = (float4*)(g_Q + (n0 + nl) * DOUT + dg);
#pragma unroll
    for (int j = 0; j < 4; ++j) {
        P4[j] = make_float4(accP[j*4+0], accP[j*4+1], accP[j*4+2], accP[j*4+3]);
        Q4[j] = make_float4(accQ[j*4+0], accQ[j*4+1], accQ[j*4+2], accQ[j*4+3]);
    }

    if (tid < 64) {
        float uu = 0.f, vv = 0.f;
#pragma unroll 8
        for (int k = 0; k < DI; ++k) {
            float xv = sx[k * 64 + tid];
            uu += xv * __ldg(&Ww[k]);
            vv += xv * __ldg(&Ww[DI + k]);
        }
        g_eu[n0 + tid] = expf(uu);
        g_v[n0 + tid]  = vv;
    }
}

// ---------------------------------------------------------------------------
// K1 (k_scan): PURE streaming scan, EXACT R6 form (two accumulators:
// weighted sum + presence). Full 1 GB as float4, .cs streaming, no atomics.
// grid (64, 64) = 4096 tiles of 32 rows.
// ---------------------------------------------------------------------------
__global__ void __launch_bounds__(256) k_scan(const float4* __restrict__ src4,
                                              const float4* __restrict__ tgt4) {
    const int g4 = blockIdx.x * blockDim.x + threadIdx.x;
    const int r0 = blockIdx.y * RCHUNK;
    const int stride4 = EDGES / 4;                          // 16384
    size_t base = (size_t)r0 * stride4 + g4;

    float4 ws = {0.f,0.f,0.f,0.f}, wt = {0.f,0.f,0.f,0.f};  // sum n*v
    float4 ps = {0.f,0.f,0.f,0.f}, pt = {0.f,0.f,0.f,0.f};  // sum v

#pragma unroll 8
    for (int n = 0; n < RCHUNK; ++n) {
        float fn = (float)(r0 + n);
        float4 vs = __ldcs(&src4[base]);
        float4 vt = __ldcs(&tgt4[base]);
        base += stride4;
        ws.x += vs.x * fn; ws.y += vs.y * fn; ws.z += vs.z * fn; ws.w += vs.w * fn;
        ps.x += vs.x;      ps.y += vs.y;      ps.z += vs.z;      ps.w += vs.w;
        wt.x += vt.x * fn; wt.y += vt.y * fn; wt.z += vt.z * fn; wt.w += vt.w * fn;
        pt.x += vt.x;      pt.y += vt.y;      pt.z += vt.z;      pt.w += vt.w;
    }
    int e0 = g4 * 4;
    if (ps.x > 0.5f) g_si[e0 + 0] = (int)(ws.x + 0.5f);
    if (ps.y > 0.5f) g_si[e0 + 1] = (int)(ws.y + 0.5f);
    if (ps.z > 0.5f) g_si[e0 + 2] = (int)(ws.z + 0.5f);
    if (ps.w > 0.5f) g_si[e0 + 3] = (int)(ws.w + 0.5f);
    if (pt.x > 0.5f) g_ti[e0 + 0] = (int)(wt.x + 0.5f);
    if (pt.y > 0.5f) g_ti[e0 + 1] = (int)(wt.y + 0.5f);
    if (pt.z > 0.5f) g_ti[e0 + 2] = (int)(wt.z + 0.5f);
    if (pt.w > 0.5f) g_ti[e0 + 3] = (int)(wt.w + 0.5f);
}

// ---------------------------------------------------------------------------
// K2 (k_build): target adjacency lists storing the SOURCE node id directly.
// ---------------------------------------------------------------------------
__global__ void __launch_bounds__(256) k_build() {
    int e = blockIdx.x * blockDim.x + threadIdx.x;
    int t = g_ti[e];
    int s = g_si[e];
    int slot = atomicAdd(&g_cnt[t], 1);
    g_adj[t * CAP + slot] = s;
}

// ---------------------------------------------------------------------------
// K3 (k_gather): 4 warps per node (block = 8 warps = 2 nodes), lane = 2 dims.
// Each warp strides over its quarter of the edge list (~8 iters), partials
// combined in smem. ae = eu[s] * evt with evt factored out of the ratio.
// 1024 blocks -> 8192 warps -> latency well hidden.
// ---------------------------------------------------------------------------
__global__ void __launch_bounds__(256) k_gather(const float* __restrict__ bf,
                                                const float* __restrict__ bw,
                                                float* __restrict__ out) {
    __shared__ float2 sacc[8][32];
    __shared__ float  sasum[8];

    const int warp = threadIdx.x >> 5;        // 0..7
    const int lane = threadIdx.x & 31;
    const int nl   = warp >> 2;                // node within block (0..1)
    const int wq   = warp & 3;                 // quarter id
    const int t    = blockIdx.x * 2 + nl;
    const int deg  = g_cnt[t];

    float2 acc = make_float2(0.f, 0.f);
    float  asum = 0.f;
    const int* adj = g_adj + t * CAP;
    const float2* P2 = (const float2*)g_P;

    int i = wq;
    for (; i + 8 <= deg; i += 8) {             // 2 chains in flight per warp
        int s0 = adj[i], s1 = adj[i + 4];
        float a0 = g_eu[s0], a1 = g_eu[s1];
        float2 p0 = P2[s0 * 32 + lane];
        float2 p1 = P2[s1 * 32 + lane];
        acc.x += a0 * fmaxf(p0.x, 0.f) * 0.f;  // placeholder removed below
        // (never emitted; see real code below)
        (void)a1; (void)p1;
        break;                                  // unreachable safeguard
    }
    // real loop (simple stride-4; 4 warps give 4 independent chains already)
    acc = make_float2(0.f, 0.f); asum = 0.f;
    {
        float2 q = ((const float2*)g_Q)[t * 32 + lane];
        float2 b = __ldg(&((const float2*)bf)[lane]);
        const float c = q.x + b.x;
        const float d = q.y + b.y;
        for (int k = wq; k < deg; k += 4) {
            int s = adj[k];
            float a = g_eu[s];
            float2 p = P2[s * 32 + lane];
            acc.x += a * fmaxf(p.x + c, 0.f);
            acc.y += a * fmaxf(p.y + d, 0.f);
            asum  += a;
        }
    }
    sacc[warp][lane] = acc;
    if (lane == 0) sasum[warp] = asum;
    __syncthreads();

    if (wq == 0) {
        int wb = nl * 4;
        float2 a0 = sacc[wb + 0][lane], a1 = sacc[wb + 1][lane];
        float2 a2 = sacc[wb + 2][lane], a3 = sacc[wb + 3][lane];
        float ax = (a0.x + a1.x) + (a2.x + a3.x);
        float ay = (a0.y + a1.y) + (a2.y + a3.y);
        float as = (sasum[wb + 0] + sasum[wb + 1]) +
                   (sasum[wb + 2] + sasum[wb + 3]);
        const float evt = expf(g_v[t] + __ldg(bw));
        // ae = eu*evt for every edge of t: factor evt out (exact except eps)
        float inv = evt / (evt * as + EPSV);
        ((float2*)out)[t * 32 + lane] = make_float2(ax * inv, ay * inv);
        if (lane == 0) g_cnt[t] = 0;           // self-clean for next replay
    }
}

// ---------------------------------------------------------------------------
extern "C" void kernel_launch(void* const* d_in, const int* in_sizes, int n_in,
                              void* d_out, int out_size) {
    const float* x   = (const float*)d_in[0];
    const float* src = (const float*)d_in[1];
    const float* tgt = (const float*)d_in[2];
    const float* Wf  = (const float*)d_in[3];
    const float* bf  = (const float*)d_in[4];
    const float* Ww  = (const float*)d_in[5];
    const float* bw  = (const float*)d_in[6];
    float* out = (float*)d_out;

    // side stream + events, created once on the (uncaptured) first call
    static cudaStream_t s2 = nullptr;
    static cudaEvent_t ev_fork = nullptr, ev_join = nullptr;
    if (s2 == nullptr) {
        cudaStreamCreateWithFlags(&s2, cudaStreamNonBlocking);
        cudaEventCreateWithFlags(&ev_fork, cudaEventDisableTiming);
        cudaEventCreateWithFlags(&ev_join, cudaEventDisableTiming);
    }

    // fork: k_pre (projections) overlaps the HBM-bound scan
    cudaEventRecord(ev_fork, 0);
    cudaStreamWaitEvent(s2, ev_fork, 0);
    k_pre<<<NODESN / 64, 256, 0, s2>>>(x, Wf, Ww);
    cudaEventRecord(ev_join, s2);

    k_scan<<<dim3(EDGES / 4 / 256, NODESN / RCHUNK), 256>>>(
        (const float4*)src, (const float4*)tgt);
    k_build<<<EDGES / 256, 256>>>();

    // join: gather needs scan+build (adjacency) and pre (P,Q,eu,v)
    cudaStreamWaitEvent(0, ev_join, 0);
    k_gather<<<NODESN / 2, 256>>>(bf, bw, out);
}